// round 10
// baseline (speedup 1.0000x reference)
#include <cuda_runtime.h>
#include <math.h>
#include <stdint.h>

// Problem-fixed sizes: N=100000, E=3200000, NF=16, H=32, HO=64
#define NMAX 100000
#define NF 16
#define H  32
#define HO 64
#define NBANK 8

__device__ float  g_agg[NMAX * NF];
__device__ float  g_h1 [NMAX * H];
__device__ float  g_h2 [NMAX * H];
__device__ double g_s1 [NBANK * 64];   // per-bank: sum[32], sumsq[32]
__device__ double g_s2 [NBANK * 64];
__device__ int    g_is64;

__device__ __forceinline__ float gelu_exact(float v) {
    return 0.5f * v * (1.0f + erff(v * 0.70710678118654752f));
}

// ---------------------------------------------------------------------------
// K0a: zero g_agg
// ---------------------------------------------------------------------------
__global__ __launch_bounds__(256) void k_pre_a(int n4) {
    int i = blockIdx.x * blockDim.x + threadIdx.x;
    if (i < n4) ((float4*)g_agg)[i] = make_float4(0.f, 0.f, 0.f, 0.f);
}
// K0b: zero banked stats
__global__ void k_pre_b() {
    int i = threadIdx.x;
    #pragma unroll
    for (int k = 0; k < NBANK * 64 / 256; k++) {
        g_s1[i + k * 256] = 0.0;
        g_s2[i + k * 256] = 0.0;
    }
}
// K0c: detect edge_index dtype
__global__ void k_pre_c(const int* __restrict__ eidx32) {
    if (threadIdx.x == 0) {
        int nz = 0;
        #pragma unroll
        for (int k = 0; k < 64; k++) nz |= eidx32[2 * k + 1];
        g_is64 = (nz == 0) ? 1 : 0;
    }
}

// ---------------------------------------------------------------------------
// K1: edge kernel. 8 THREADS PER EDGE (c = t&7 handles features [2c,2c+2)),
// grid-stride + index prefetch. Weight chunk w[8][2] = 16 regs -> occupancy
// rises past the 64-reg/4-block ceiling of the 4-thr/edge version.
// Gather LDG.64, scatter atomicAdd(float2) (sm_90+ RED.64).
// ---------------------------------------------------------------------------
__global__ __launch_bounds__(256) void k_edge(const float* __restrict__ x,
                                              const void*  __restrict__ eidx,
                                              const float* __restrict__ ea,
                                              const float* __restrict__ We,
                                              const float* __restrict__ be,
                                              int E) {
    int t = blockIdx.x * blockDim.x + threadIdx.x;
    int c = t & 7;

    // per-thread weight chunk: We[k][2c..2c+2), k = 0..7  (16 regs)
    float w[8][2];
    #pragma unroll
    for (int k = 0; k < 8; k++) {
        float2 wv = __ldg((const float2*)(We + k * 16) + c);
        w[k][0] = wv.x; w[k][1] = wv.y;
    }
    float2 bv = __ldg(((const float2*)be) + c);
    int is64 = g_is64;

    int total  = E * 8;
    int stride = gridDim.x * blockDim.x;   // multiple of 8
    const int*       p32 = (const int*)eidx;
    const long long* p64 = (const long long*)eidx;

    int gt = t;
    if (gt >= total) return;

    int src, dst;
    {
        int e = gt >> 3;
        if (is64) { src = (int)__ldcs(p64 + e); dst = (int)__ldcs(p64 + e + E); }
        else      { src = __ldcs(p32 + e);      dst = __ldcs(p32 + e + E);      }
    }

    while (gt < total) {
        int gtn = gt + stride;
        int srcN = 0, dstN = 0;
        if (gtn < total) {
            int en = gtn >> 3;
            if (is64) { srcN = (int)__ldcs(p64 + en); dstN = (int)__ldcs(p64 + en + E); }
            else      { srcN = __ldcs(p32 + en);      dstN = __ldcs(p32 + en + E);      }
        }

        int e = gt >> 3;
        float2 xv = __ldg((const float2*)(x + (size_t)src * 16) + c);
        const float4* ear = (const float4*)(ea + (size_t)e * 8);
        float4 a0 = __ldcs(ear);
        float4 a1 = __ldcs(ear + 1);
        float av[8] = {a0.x, a0.y, a0.z, a0.w, a1.x, a1.y, a1.z, a1.w};

        float m0 = bv.x, m1 = bv.y;
        #pragma unroll
        for (int k = 0; k < 8; k++) {
            m0 = fmaf(av[k], w[k][0], m0);
            m1 = fmaf(av[k], w[k][1], m1);
        }

        float2 r;
        r.x = fmaxf(xv.x + m0, 0.0f);
        r.y = fmaxf(xv.y + m1, 0.0f);
        atomicAdd((float2*)(g_agg + (size_t)dst * 16) + c, r);

        gt = gtn; src = srcN; dst = dstN;
    }
}

// ---------------------------------------------------------------------------
// stats epilogue: half-transpose reduction, banked double atomics
// ---------------------------------------------------------------------------
__device__ __forceinline__ void stats_epilogue(const float* acc, bool valid,
                                               double* sums) {
    __shared__ float tr[8][16][33];
    __shared__ float comb[8][32];
    int lane = threadIdx.x & 31;
    int wid  = threadIdx.x >> 5;
    int f    = lane & 15;
    bool isq = lane >= 16;
    int bank = blockIdx.x & (NBANK - 1);

    float red[2];
    #pragma unroll
    for (int half = 0; half < 2; half++) {
        if (half) __syncwarp();
        #pragma unroll
        for (int j = 0; j < 16; j++)
            tr[wid][j][lane] = valid ? acc[half * 16 + j] : 0.0f;
        __syncwarp();
        float r = 0.0f;
        #pragma unroll
        for (int k = 0; k < 32; k++) {
            float v = tr[wid][f][k];
            r = fmaf(v, isq ? v : 1.0f, r);
        }
        red[half] = r;
    }

    #pragma unroll
    for (int half = 0; half < 2; half++) {
        comb[wid][lane] = red[half];
        __syncthreads();
        if (wid == 0) {
            float tsum = 0.0f;
            #pragma unroll
            for (int w = 0; w < 8; w++) tsum += comb[w][lane];
            atomicAdd(&sums[bank * 64 + (isq ? 32 : 0) + half * 16 + f],
                      (double)tsum);
        }
        __syncthreads();
    }
}

// ---------------------------------------------------------------------------
// BN finalize inline: sum the 8 banks, then scale/shift
// ---------------------------------------------------------------------------
__device__ __forceinline__ void fin_inline(const double* __restrict__ sums,
                                           const float* __restrict__ gamma,
                                           const float* __restrict__ beta,
                                           int N, float* ssc, float* ssh) {
    if (threadIdx.x < H) {
        int f = threadIdx.x;
        double s = 0.0, q = 0.0;
        #pragma unroll
        for (int b = 0; b < NBANK; b++) {
            s += sums[b * 64 + f];
            q += sums[b * 64 + 32 + f];
        }
        double mean = s / (double)N;
        double var  = q / (double)N - mean * mean;
        double inv  = 1.0 / sqrt(var + 1e-5);
        ssc[f] = (float)((double)gamma[f] * inv);
        ssh[f] = (float)((double)beta[f] - mean * (double)gamma[f] * inv);
    }
}

// ---------------------------------------------------------------------------
// K2: h1 = ((1+eps)*x + agg) @ W1 + b1   (+ fused BN1 stats, streamed)
// ---------------------------------------------------------------------------
__global__ __launch_bounds__(256) void k_gemm1(const float* __restrict__ x,
                                               const float* __restrict__ epsp,
                                               const float* __restrict__ W1,
                                               const float* __restrict__ b1,
                                               int N) {
    __shared__ float sW[NF * H];
    __shared__ float sb[H];
    for (int i = threadIdx.x; i < NF * H; i += blockDim.x) sW[i] = W1[i];
    if (threadIdx.x < H) sb[threadIdx.x] = b1[threadIdx.x];
    __syncthreads();

    int n = blockIdx.x * blockDim.x + threadIdx.x;
    bool valid = n < N;
    float sc = 1.0f + epsp[0];
    int nc = valid ? n : 0;

    const float4* ar = (const float4*)(g_agg + (size_t)nc * NF);
    const float4* xr = (const float4*)(x     + (size_t)nc * NF);

    float acc[H];
    #pragma unroll
    for (int j = 0; j < H; j++) acc[j] = sb[j];

    #pragma unroll 1
    for (int cph = 0; cph < 4; cph++) {
        float4 v  = ar[cph];
        float4 xv = xr[cph];
        float a0 = fmaf(sc, xv.x, v.x);
        float a1 = fmaf(sc, xv.y, v.y);
        float a2 = fmaf(sc, xv.z, v.z);
        float a3 = fmaf(sc, xv.w, v.w);
        const float* w0 = sW + (4 * cph + 0) * H;
        const float* w1 = sW + (4 * cph + 1) * H;
        const float* w2 = sW + (4 * cph + 2) * H;
        const float* w3 = sW + (4 * cph + 3) * H;
        #pragma unroll
        for (int j = 0; j < H; j++) {
            float t0 = fmaf(a0, w0[j], acc[j]);
            float t1 = fmaf(a1, w1[j], t0);
            float t2 = fmaf(a2, w2[j], t1);
            acc[j]   = fmaf(a3, w3[j], t2);
        }
    }

    if (valid) {
        float4* hr = (float4*)(g_h1 + (size_t)n * H);
        #pragma unroll
        for (int cph = 0; cph < H / 4; cph++)
            hr[cph] = make_float4(acc[4*cph], acc[4*cph+1], acc[4*cph+2], acc[4*cph+3]);
    }
    stats_epilogue(acc, valid, g_s1);
}

// ---------------------------------------------------------------------------
// K3: h2 = gelu(bn1(h1)) @ W2 + b2   (streamed; BN1 inline; fused BN2 stats)
// ---------------------------------------------------------------------------
__global__ __launch_bounds__(256) void k_gemm2(const float* __restrict__ g1,
                                               const float* __restrict__ bt1,
                                               const float* __restrict__ W2,
                                               const float* __restrict__ b2,
                                               int N) {
    __shared__ float sW[H * H];
    __shared__ float sb[H], ssc[H], ssh[H];
    for (int i = threadIdx.x; i < H * H; i += blockDim.x) sW[i] = W2[i];
    if (threadIdx.x < H) sb[threadIdx.x] = b2[threadIdx.x];
    fin_inline(g_s1, g1, bt1, N, ssc, ssh);
    __syncthreads();

    int n = blockIdx.x * blockDim.x + threadIdx.x;
    bool valid = n < N;
    int nc = valid ? n : 0;
    const float4* hr = (const float4*)(g_h1 + (size_t)nc * H);

    float acc[H];
    #pragma unroll
    for (int j = 0; j < H; j++) acc[j] = sb[j];

    #pragma unroll 1
    for (int cph = 0; cph < 8; cph++) {
        float4 v = hr[cph];
        float y0 = gelu_exact(fmaf(v.x, ssc[4*cph+0], ssh[4*cph+0]));
        float y1 = gelu_exact(fmaf(v.y, ssc[4*cph+1], ssh[4*cph+1]));
        float y2 = gelu_exact(fmaf(v.z, ssc[4*cph+2], ssh[4*cph+2]));
        float y3 = gelu_exact(fmaf(v.w, ssc[4*cph+3], ssh[4*cph+3]));
        const float* w0 = sW + (4 * cph + 0) * H;
        const float* w1 = sW + (4 * cph + 1) * H;
        const float* w2 = sW + (4 * cph + 2) * H;
        const float* w3 = sW + (4 * cph + 3) * H;
        #pragma unroll
        for (int j = 0; j < H; j++) {
            float t0 = fmaf(y0, w0[j], acc[j]);
            float t1 = fmaf(y1, w1[j], t0);
            float t2 = fmaf(y2, w2[j], t1);
            acc[j]   = fmaf(y3, w3[j], t2);
        }
    }

    if (valid) {
        float4* o = (float4*)(g_h2 + (size_t)n * H);
        #pragma unroll
        for (int cph = 0; cph < H / 4; cph++)
            o[cph] = make_float4(acc[4*cph], acc[4*cph+1], acc[4*cph+2], acc[4*cph+3]);
    }
    stats_epilogue(acc, valid, g_s2);
}

// ---------------------------------------------------------------------------
// K4: out = gelu(bn2(h2)) @ W3 + b3   (gelu once into y[32]; 2 output passes)
// ---------------------------------------------------------------------------
__global__ __launch_bounds__(256) void k_out(const float* __restrict__ g2,
                                             const float* __restrict__ bt2,
                                             const float* __restrict__ W3,
                                             const float* __restrict__ b3,
                                             float* __restrict__ out,
                                             int N) {
    __shared__ float sW[H * HO];
    __shared__ float sb[HO], ssc[H], ssh[H];
    for (int i = threadIdx.x; i < H * HO; i += blockDim.x) sW[i] = W3[i];
    if (threadIdx.x < HO) sb[threadIdx.x] = b3[threadIdx.x];
    fin_inline(g_s2, g2, bt2, N, ssc, ssh);
    __syncthreads();

    int n = blockIdx.x * blockDim.x + threadIdx.x;
    if (n >= N) return;
    const float4* hr = (const float4*)(g_h2 + (size_t)n * H);
    float4* orow = (float4*)(out + (size_t)n * HO);

    float y[H];
    #pragma unroll
    for (int cph = 0; cph < 8; cph++) {
        float4 v = hr[cph];
        y[4*cph+0] = gelu_exact(fmaf(v.x, ssc[4*cph+0], ssh[4*cph+0]));
        y[4*cph+1] = gelu_exact(fmaf(v.y, ssc[4*cph+1], ssh[4*cph+1]));
        y[4*cph+2] = gelu_exact(fmaf(v.z, ssc[4*cph+2], ssh[4*cph+2]));
        y[4*cph+3] = gelu_exact(fmaf(v.w, ssc[4*cph+3], ssh[4*cph+3]));
    }

    #pragma unroll 1
    for (int jb = 0; jb < 2; jb++) {
        float acc[32];
        #pragma unroll
        for (int j = 0; j < 32; j++) acc[j] = sb[jb * 32 + j];
        #pragma unroll
        for (int k = 0; k < H; k++) {
            const float* wr = sW + k * HO + jb * 32;
            #pragma unroll
            for (int j = 0; j < 32; j++) acc[j] = fmaf(y[k], wr[j], acc[j]);
        }
        #pragma unroll
        for (int cph = 0; cph < 8; cph++)
            orow[jb * 8 + cph] = make_float4(acc[4*cph], acc[4*cph+1],
                                             acc[4*cph+2], acc[4*cph+3]);
    }
}

// ---------------------------------------------------------------------------
extern "C" void kernel_launch(void* const* d_in, const int* in_sizes, int n_in,
                              void* d_out, int out_size) {
    const float* x    = (const float*)d_in[0];
    const void*  eidx =               d_in[1];
    const float* ea   = (const float*)d_in[2];
    const float* We   = (const float*)d_in[3];
    const float* be   = (const float*)d_in[4];
    const float* W1   = (const float*)d_in[5];
    const float* b1   = (const float*)d_in[6];
    const float* g1   = (const float*)d_in[7];
    const float* bt1  = (const float*)d_in[8];
    const float* W2   = (const float*)d_in[9];
    const float* b2   = (const float*)d_in[10];
    const float* epsp = (const float*)d_in[11];
    const float* g2   = (const float*)d_in[12];
    const float* bt2  = (const float*)d_in[13];
    const float* W3   = (const float*)d_in[14];
    const float* b3   = (const float*)d_in[15];
    float* out = (float*)d_out;

    int N = in_sizes[0] / NF;
    int E = in_sizes[2] / 8;
    int n4 = N * NF / 4;
    int nb = (N + 255) / 256;

    k_pre_a<<<(n4 + 255) / 256, 256>>>(n4);
    k_pre_b<<<1, 256>>>();
    k_pre_c<<<1, 32>>>((const int*)eidx);
    k_edge <<<2048, 256>>>(x, eidx, ea, We, be, E);   // profiled (launch idx 3)
    k_gemm1<<<nb, 256>>>(x, epsp, W1, b1, N);
    k_gemm2<<<nb, 256>>>(g1, bt1, W2, b2, N);
    k_out  <<<nb, 256>>>(g2, bt2, W3, b3, out, N);
}

// round 11
// speedup vs baseline: 1.1696x; 1.1696x over previous
#include <cuda_runtime.h>
#include <math.h>
#include <stdint.h>

// Problem-fixed sizes: N=100000, E=3200000, NF=16, H=32, HO=64
#define NMAX 100000
#define NF 16
#define H  32
#define HO 64
#define NBANK 8

__device__ float  g_agg[NMAX * NF];
__device__ float  g_h1 [NMAX * H];
__device__ float  g_h2 [NMAX * H];
__device__ double g_s1 [NBANK * 64];   // per-bank: sum[32], sumsq[32]
__device__ double g_s2 [NBANK * 64];
__device__ int    g_is64;

__device__ __forceinline__ float gelu_exact(float v) {
    return 0.5f * v * (1.0f + erff(v * 0.70710678118654752f));
}

// ---------------------------------------------------------------------------
// K0a: zero g_agg
// ---------------------------------------------------------------------------
__global__ __launch_bounds__(256) void k_pre_a(int n4) {
    int i = blockIdx.x * blockDim.x + threadIdx.x;
    if (i < n4) ((float4*)g_agg)[i] = make_float4(0.f, 0.f, 0.f, 0.f);
}
// K0b: zero banked stats + detect edge_index dtype
__global__ void k_pre_b(const int* __restrict__ eidx32) {
    int i = threadIdx.x;
    #pragma unroll
    for (int k = 0; k < NBANK * 64 / 256; k++) {
        g_s1[i + k * 256] = 0.0;
        g_s2[i + k * 256] = 0.0;
    }
    if (i == 0) {
        int nz = 0;
        #pragma unroll
        for (int k = 0; k < 64; k++) nz |= eidx32[2 * k + 1];
        g_is64 = (nz == 0) ? 1 : 0;
    }
}

// ---------------------------------------------------------------------------
// K1: edge kernel (R9 config: 4 threads/edge, grid-stride, index prefetch,
// weights in registers, __ldcs streaming for idx/ea).
// ---------------------------------------------------------------------------
__global__ __launch_bounds__(256) void k_edge(const float* __restrict__ x,
                                              const void*  __restrict__ eidx,
                                              const float* __restrict__ ea,
                                              const float* __restrict__ We,
                                              const float* __restrict__ be,
                                              int E) {
    int t = blockIdx.x * blockDim.x + threadIdx.x;
    int c = t & 3;

    float w[8][4];
    #pragma unroll
    for (int k = 0; k < 8; k++) {
        float4 wv = __ldg((const float4*)(We + k * 16) + c);
        w[k][0] = wv.x; w[k][1] = wv.y; w[k][2] = wv.z; w[k][3] = wv.w;
    }
    float4 bv = __ldg(((const float4*)be) + c);
    int is64 = g_is64;

    int total  = E * 4;
    int stride = gridDim.x * blockDim.x;   // multiple of 4
    const int*       p32 = (const int*)eidx;
    const long long* p64 = (const long long*)eidx;

    int gt = t;
    if (gt >= total) return;

    int src, dst;
    {
        int e = gt >> 2;
        if (is64) { src = (int)__ldcs(p64 + e); dst = (int)__ldcs(p64 + e + E); }
        else      { src = __ldcs(p32 + e);      dst = __ldcs(p32 + e + E);      }
    }

    while (gt < total) {
        int gtn = gt + stride;
        int srcN = 0, dstN = 0;
        if (gtn < total) {
            int en = gtn >> 2;
            if (is64) { srcN = (int)__ldcs(p64 + en); dstN = (int)__ldcs(p64 + en + E); }
            else      { srcN = __ldcs(p32 + en);      dstN = __ldcs(p32 + en + E);      }
        }

        int e = gt >> 2;
        float4 xv = __ldg((const float4*)(x + (size_t)src * 16) + c);
        const float4* ear = (const float4*)(ea + (size_t)e * 8);
        float4 a0 = __ldcs(ear);
        float4 a1 = __ldcs(ear + 1);
        float av[8] = {a0.x, a0.y, a0.z, a0.w, a1.x, a1.y, a1.z, a1.w};

        float m0 = bv.x, m1 = bv.y, m2 = bv.z, m3 = bv.w;
        #pragma unroll
        for (int k = 0; k < 8; k++) {
            m0 = fmaf(av[k], w[k][0], m0);
            m1 = fmaf(av[k], w[k][1], m1);
            m2 = fmaf(av[k], w[k][2], m2);
            m3 = fmaf(av[k], w[k][3], m3);
        }

        float4 r;
        r.x = fmaxf(xv.x + m0, 0.0f);
        r.y = fmaxf(xv.y + m1, 0.0f);
        r.z = fmaxf(xv.z + m2, 0.0f);
        r.w = fmaxf(xv.w + m3, 0.0f);
        atomicAdd((float4*)(g_agg + (size_t)dst * 16) + c, r);

        gt = gtn; src = srcN; dst = dstN;
    }
}

// ---------------------------------------------------------------------------
// stats epilogue: half-transpose reduction, banked double atomics
// ---------------------------------------------------------------------------
__device__ __forceinline__ void stats_epilogue(const float* acc, bool valid,
                                               double* sums) {
    __shared__ float tr[8][16][33];
    __shared__ float comb[8][32];
    int lane = threadIdx.x & 31;
    int wid  = threadIdx.x >> 5;
    int f    = lane & 15;
    bool isq = lane >= 16;
    int bank = blockIdx.x & (NBANK - 1);

    float red[2];
    #pragma unroll
    for (int half = 0; half < 2; half++) {
        if (half) __syncwarp();
        #pragma unroll
        for (int j = 0; j < 16; j++)
            tr[wid][j][lane] = valid ? acc[half * 16 + j] : 0.0f;
        __syncwarp();
        float r = 0.0f;
        #pragma unroll
        for (int k = 0; k < 32; k++) {
            float v = tr[wid][f][k];
            r = fmaf(v, isq ? v : 1.0f, r);
        }
        red[half] = r;
    }

    #pragma unroll
    for (int half = 0; half < 2; half++) {
        comb[wid][lane] = red[half];
        __syncthreads();
        if (wid == 0) {
            float tsum = 0.0f;
            #pragma unroll
            for (int w = 0; w < 8; w++) tsum += comb[w][lane];
            atomicAdd(&sums[bank * 64 + (isq ? 32 : 0) + half * 16 + f],
                      (double)tsum);
        }
        __syncthreads();
    }
}

// ---------------------------------------------------------------------------
// BN finalize inline: sum the 8 banks, then scale/shift
// ---------------------------------------------------------------------------
__device__ __forceinline__ void fin_inline(const double* __restrict__ sums,
                                           const float* __restrict__ gamma,
                                           const float* __restrict__ beta,
                                           int N, float* ssc, float* ssh) {
    if (threadIdx.x < H) {
        int f = threadIdx.x;
        double s = 0.0, q = 0.0;
        #pragma unroll
        for (int b = 0; b < NBANK; b++) {
            s += sums[b * 64 + f];
            q += sums[b * 64 + 32 + f];
        }
        double mean = s / (double)N;
        double var  = q / (double)N - mean * mean;
        double inv  = 1.0 / sqrt(var + 1e-5);
        ssc[f] = (float)((double)gamma[f] * inv);
        ssh[f] = (float)((double)beta[f] - mean * (double)gamma[f] * inv);
    }
}

// ---------------------------------------------------------------------------
// K2: h1 = ((1+eps)*x + agg) @ W1 + b1   (+ fused BN1 stats, streamed)
// ---------------------------------------------------------------------------
__global__ __launch_bounds__(256, 4) void k_gemm1(const float* __restrict__ x,
                                                  const float* __restrict__ epsp,
                                                  const float* __restrict__ W1,
                                                  const float* __restrict__ b1,
                                                  int N) {
    __shared__ float sW[NF * H];
    __shared__ float sb[H];
    for (int i = threadIdx.x; i < NF * H; i += blockDim.x) sW[i] = W1[i];
    if (threadIdx.x < H) sb[threadIdx.x] = b1[threadIdx.x];
    __syncthreads();

    int n = blockIdx.x * blockDim.x + threadIdx.x;
    bool valid = n < N;
    float sc = 1.0f + epsp[0];
    int nc = valid ? n : 0;

    const float4* ar = (const float4*)(g_agg + (size_t)nc * NF);
    const float4* xr = (const float4*)(x     + (size_t)nc * NF);

    float acc[H];
    #pragma unroll
    for (int j = 0; j < H; j++) acc[j] = sb[j];

    #pragma unroll 1
    for (int cph = 0; cph < 4; cph++) {
        float4 v  = ar[cph];
        float4 xv = xr[cph];
        float a0 = fmaf(sc, xv.x, v.x);
        float a1 = fmaf(sc, xv.y, v.y);
        float a2 = fmaf(sc, xv.z, v.z);
        float a3 = fmaf(sc, xv.w, v.w);
        const float* w0 = sW + (4 * cph + 0) * H;
        const float* w1 = sW + (4 * cph + 1) * H;
        const float* w2 = sW + (4 * cph + 2) * H;
        const float* w3 = sW + (4 * cph + 3) * H;
        #pragma unroll
        for (int j = 0; j < H; j++) {
            float t0 = fmaf(a0, w0[j], acc[j]);
            float t1 = fmaf(a1, w1[j], t0);
            float t2 = fmaf(a2, w2[j], t1);
            acc[j]   = fmaf(a3, w3[j], t2);
        }
    }

    if (valid) {
        float4* hr = (float4*)(g_h1 + (size_t)n * H);
        #pragma unroll
        for (int cph = 0; cph < H / 4; cph++)
            hr[cph] = make_float4(acc[4*cph], acc[4*cph+1], acc[4*cph+2], acc[4*cph+3]);
    }
    stats_epilogue(acc, valid, g_s1);
}

// ---------------------------------------------------------------------------
// K3: h2 = gelu(bn1(h1)) @ W2 + b2   (streamed; BN1 inline; fused BN2 stats)
// ---------------------------------------------------------------------------
__global__ __launch_bounds__(256, 4) void k_gemm2(const float* __restrict__ g1,
                                                  const float* __restrict__ bt1,
                                                  const float* __restrict__ W2,
                                                  const float* __restrict__ b2,
                                                  int N) {
    __shared__ float sW[H * H];
    __shared__ float sb[H], ssc[H], ssh[H];
    for (int i = threadIdx.x; i < H * H; i += blockDim.x) sW[i] = W2[i];
    if (threadIdx.x < H) sb[threadIdx.x] = b2[threadIdx.x];
    fin_inline(g_s1, g1, bt1, N, ssc, ssh);
    __syncthreads();

    int n = blockIdx.x * blockDim.x + threadIdx.x;
    bool valid = n < N;
    int nc = valid ? n : 0;
    const float4* hr = (const float4*)(g_h1 + (size_t)nc * H);

    float acc[H];
    #pragma unroll
    for (int j = 0; j < H; j++) acc[j] = sb[j];

    #pragma unroll 1
    for (int cph = 0; cph < 8; cph++) {
        float4 v = hr[cph];
        float y0 = gelu_exact(fmaf(v.x, ssc[4*cph+0], ssh[4*cph+0]));
        float y1 = gelu_exact(fmaf(v.y, ssc[4*cph+1], ssh[4*cph+1]));
        float y2 = gelu_exact(fmaf(v.z, ssc[4*cph+2], ssh[4*cph+2]));
        float y3 = gelu_exact(fmaf(v.w, ssc[4*cph+3], ssh[4*cph+3]));
        const float* w0 = sW + (4 * cph + 0) * H;
        const float* w1 = sW + (4 * cph + 1) * H;
        const float* w2 = sW + (4 * cph + 2) * H;
        const float* w3 = sW + (4 * cph + 3) * H;
        #pragma unroll
        for (int j = 0; j < H; j++) {
            float t0 = fmaf(y0, w0[j], acc[j]);
            float t1 = fmaf(y1, w1[j], t0);
            float t2 = fmaf(y2, w2[j], t1);
            acc[j]   = fmaf(y3, w3[j], t2);
        }
    }

    if (valid) {
        float4* o = (float4*)(g_h2 + (size_t)n * H);
        #pragma unroll
        for (int cph = 0; cph < H / 4; cph++)
            o[cph] = make_float4(acc[4*cph], acc[4*cph+1], acc[4*cph+2], acc[4*cph+3]);
    }
    stats_epilogue(acc, valid, g_s2);
}

// ---------------------------------------------------------------------------
// K4: out = gelu(bn2(h2)) @ W3 + b3   (y[32] once; 4 passes of acc[16])
// ---------------------------------------------------------------------------
__global__ __launch_bounds__(256, 4) void k_out(const float* __restrict__ g2,
                                                const float* __restrict__ bt2,
                                                const float* __restrict__ W3,
                                                const float* __restrict__ b3,
                                                float* __restrict__ out,
                                                int N) {
    __shared__ float sW[H * HO];
    __shared__ float sb[HO], ssc[H], ssh[H];
    for (int i = threadIdx.x; i < H * HO; i += blockDim.x) sW[i] = W3[i];
    if (threadIdx.x < HO) sb[threadIdx.x] = b3[threadIdx.x];
    fin_inline(g_s2, g2, bt2, N, ssc, ssh);
    __syncthreads();

    int n = blockIdx.x * blockDim.x + threadIdx.x;
    if (n >= N) return;
    const float4* hr = (const float4*)(g_h2 + (size_t)n * H);
    float4* orow = (float4*)(out + (size_t)n * HO);

    float y[H];
    #pragma unroll
    for (int cph = 0; cph < 8; cph++) {
        float4 v = hr[cph];
        y[4*cph+0] = gelu_exact(fmaf(v.x, ssc[4*cph+0], ssh[4*cph+0]));
        y[4*cph+1] = gelu_exact(fmaf(v.y, ssc[4*cph+1], ssh[4*cph+1]));
        y[4*cph+2] = gelu_exact(fmaf(v.z, ssc[4*cph+2], ssh[4*cph+2]));
        y[4*cph+3] = gelu_exact(fmaf(v.w, ssc[4*cph+3], ssh[4*cph+3]));
    }

    #pragma unroll 1
    for (int jb = 0; jb < 4; jb++) {
        float acc[16];
        #pragma unroll
        for (int j = 0; j < 16; j++) acc[j] = sb[jb * 16 + j];
        #pragma unroll
        for (int k = 0; k < H; k++) {
            const float* wr = sW + k * HO + jb * 16;
            #pragma unroll
            for (int j = 0; j < 16; j++) acc[j] = fmaf(y[k], wr[j], acc[j]);
        }
        #pragma unroll
        for (int cph = 0; cph < 4; cph++)
            orow[jb * 4 + cph] = make_float4(acc[4*cph], acc[4*cph+1],
                                             acc[4*cph+2], acc[4*cph+3]);
    }
}

// ---------------------------------------------------------------------------
extern "C" void kernel_launch(void* const* d_in, const int* in_sizes, int n_in,
                              void* d_out, int out_size) {
    const float* x    = (const float*)d_in[0];
    const void*  eidx =               d_in[1];
    const float* ea   = (const float*)d_in[2];
    const float* We   = (const float*)d_in[3];
    const float* be   = (const float*)d_in[4];
    const float* W1   = (const float*)d_in[5];
    const float* b1   = (const float*)d_in[6];
    const float* g1   = (const float*)d_in[7];
    const float* bt1  = (const float*)d_in[8];
    const float* W2   = (const float*)d_in[9];
    const float* b2   = (const float*)d_in[10];
    const float* epsp = (const float*)d_in[11];
    const float* g2   = (const float*)d_in[12];
    const float* bt2  = (const float*)d_in[13];
    const float* W3   = (const float*)d_in[14];
    const float* b3   = (const float*)d_in[15];
    float* out = (float*)d_out;

    int N = in_sizes[0] / NF;
    int E = in_sizes[2] / 8;
    int n4 = N * NF / 4;
    int nb = (N + 255) / 256;

    k_pre_a<<<(n4 + 255) / 256, 256>>>(n4);
    k_pre_b<<<1, 256>>>((const int*)eidx);
    k_edge <<<2048, 256>>>(x, eidx, ea, We, be, E);
    k_gemm1<<<nb, 256>>>(x, epsp, W1, b1, N);        // profiled (launch idx 3)
    k_gemm2<<<nb, 256>>>(g1, bt1, W2, b2, N);
    k_out  <<<nb, 256>>>(g2, bt2, W3, b3, out, N);
}